// round 1
// baseline (speedup 1.0000x reference)
#include <cuda_runtime.h>
#include <cuda_bf16.h>

#define EPS 1e-6f
#define NB 16          // batches
#define NA 10          // agents
#define NT 30          // timesteps
#define NP_POLY 16     // polygons per batch
#define NV 200         // vertices per polygon
#define NSEG (NP_POLY * (NV - 1))   // 3184 segments per batch
#define NPTS_WARP 4    // points per warp
#define THREADS 256

// Precomputed per-(batch,segment) data
// g_seg4: {sx, sy, ex, ey}  (original vertex coords -> exact cond_y test)
// g_seg2: {1/(esq+eps), 1/(slope+eps)}
__device__ float4 g_seg4[NB * NSEG];
__device__ float2 g_seg2[NB * NSEG];

__global__ void precompute_kernel(const float* __restrict__ polys) {
    int idx = blockIdx.x * blockDim.x + threadIdx.x;
    if (idx >= NB * NSEG) return;
    int b = idx / NSEG;
    int s = idx - b * NSEG;
    int p = s / (NV - 1);
    int j = s - p * (NV - 1);
    const float* v = polys + (((size_t)b * NP_POLY + p) * NV + j) * 2;
    float sx = v[0], sy = v[1], ex = v[2], ey = v[3];
    float evx = ex - sx;
    float evy = ey - sy;
    float esq = evx * evx + evy * evy;
    float rcp_esq = 1.0f / (esq + EPS);
    float slope = evy / (evx + EPS);
    float rcp_sl = 1.0f / (slope + EPS);
    g_seg4[idx] = make_float4(sx, sy, ex, ey);
    g_seg2[idx] = make_float2(rcp_esq, rcp_sl);
}

__global__ __launch_bounds__(THREADS)
void offroad_main_kernel(const float* __restrict__ points, float* __restrict__ out) {
    extern __shared__ char smemraw[];
    float4* s4 = (float4*)smemraw;                       // NSEG * 16 B
    float2* s2 = (float2*)(smemraw + NSEG * 16);         // NSEG * 8 B
    float*  sl = (float*) (smemraw + NSEG * 24);         // NT floats

    int b = blockIdx.x / NA;
    int a = blockIdx.x - b * NA;

    // cooperative load of this batch's segment table
    const float4* g4 = g_seg4 + b * NSEG;
    const float2* g2 = g_seg2 + b * NSEG;
    for (int i = threadIdx.x; i < NSEG; i += THREADS) {
        s4[i] = g4[i];
        s2[i] = g2[i];
    }
    __syncthreads();

    int wid = threadIdx.x >> 5;
    int ln  = threadIdx.x & 31;
    int t0  = wid * NPTS_WARP;

    float px[NPTS_WARP], py[NPTS_WARP], md[NPTS_WARP];
    int   ct[NPTS_WARP];

    const float2* pts2 = (const float2*)points;
#pragma unroll
    for (int k = 0; k < NPTS_WARP; k++) {
        int t = t0 + k;
        float2 pt;
        if (t < NT) pt = pts2[((b * NA + a) * NT + t)];
        else        pt = make_float2(1e30f, 1e30f);
        px[k] = pt.x; py[k] = pt.y;
        md[k] = 3.4e38f;
        ct[k] = 0;
    }

    // sweep all segments of the batch: lanes stride over segments
    for (int s = ln; s < NSEG; s += 32) {
        float4 sg = s4[s];
        float2 rr = s2[s];
        float evx = sg.z - sg.x;   // bit-identical to reference ev
        float evy = sg.w - sg.y;
#pragma unroll
        for (int k = 0; k < NPTS_WARP; k++) {
            float v1x = px[k] - sg.x;
            float v1y = py[k] - sg.y;
            float dot = fmaf(v1x, evx, v1y * evy);
            float proj = __saturatef(dot * rr.x);     // clamp(dot/(esq+eps),0,1)
            float cx = fmaf(evx, proj, sg.x);
            float cy = fmaf(evy, proj, sg.y);
            float dx = px[k] - cx;
            float dy = py[k] - cy;
            float d2 = fmaf(dx, dx, dy * dy);
            md[k] = fminf(md[k], d2);
            // crossing test (exact strict/non-strict per reference)
            bool condy = ((sg.y <= py[k]) && (py[k] < sg.w)) ||
                         ((sg.w <= py[k]) && (py[k] < sg.y));
            float ix = fmaf(v1y, rr.y, sg.x);         // sx + (py-sy)/(slope+eps)
            if (condy && (ix > px[k])) ct[k]++;
        }
    }

    // warp reduction: min dist^2, crossing count
#pragma unroll
    for (int k = 0; k < NPTS_WARP; k++) {
#pragma unroll
        for (int o = 16; o > 0; o >>= 1) {
            md[k] = fminf(md[k], __shfl_xor_sync(0xffffffffu, md[k], o));
            ct[k] += __shfl_xor_sync(0xffffffffu, ct[k], o);
        }
    }

    if (ln == 0) {
#pragma unroll
        for (int k = 0; k < NPTS_WARP; k++) {
            int t = t0 + k;
            if (t < NT) {
                float d = sqrtf(fmaxf(md[k], EPS));
                if (ct[k] & 1) d = -d;
                sl[t] = fmaxf(d + 0.5f, 0.0f);
            }
        }
    }
    __syncthreads();

    // deterministic sequential sum over t
    if (threadIdx.x == 0) {
        float sum = 0.0f;
        for (int t = 0; t < NT; t++) sum += sl[t];
        out[blockIdx.x] = sum;
    }
}

extern "C" void kernel_launch(void* const* d_in, const int* in_sizes, int n_in,
                              void* d_out, int out_size) {
    const float* points = (const float*)d_in[0];  // (16,10,30,2)
    const float* polys  = (const float*)d_in[1];  // (16,16,200,2)
    float* out = (float*)d_out;                   // (16,10)

    // precompute per-segment reciprocals (division-free main loop)
    int total = NB * NSEG;
    precompute_kernel<<<(total + 255) / 256, 256>>>(polys);

    size_t smem = (size_t)NSEG * 24 + 128;  // seg4 + seg2 + loss scratch
    cudaFuncSetAttribute(offroad_main_kernel,
                         cudaFuncAttributeMaxDynamicSharedMemorySize, (int)smem);
    offroad_main_kernel<<<NB * NA, THREADS, smem>>>(points, out);
}

// round 2
// speedup vs baseline: 1.8901x; 1.8901x over previous
#include <cuda_runtime.h>
#include <cuda_bf16.h>

#define EPS 1e-6f
#define NB 16
#define NA 10
#define NT 30
#define NP_POLY 16
#define NV 200
#define SEG_PER_POLY (NV - 1)            // 199
#define NSEG (NP_POLY * SEG_PER_POLY)    // 3184
#define NPTS_WARP 8
#define WARPS 4
#define THREADS (WARPS * 32)             // 128
#define PTSLOTS (WARPS * NPTS_WARP)      // 32 >= NT

// per-(batch,segment) precomputed tables
__device__ float4 g_seg4[NB * NSEG];  // {sx, sy, ex, ey}
__device__ float2 g_seg2[NB * NSEG];  // {1/(esq+eps), 1/(slope+eps)}

// partial results: [ (b*NA+a)*PTSLOTS + t ][ poly ]
__device__ float g_md[NB * NA * PTSLOTS * NP_POLY];
__device__ int   g_ct[NB * NA * PTSLOTS * NP_POLY];

__global__ void precompute_kernel(const float* __restrict__ polys) {
    int idx = blockIdx.x * blockDim.x + threadIdx.x;
    if (idx >= NB * NSEG) return;
    int b = idx / NSEG;
    int s = idx - b * NSEG;
    int p = s / SEG_PER_POLY;
    int j = s - p * SEG_PER_POLY;
    const float* v = polys + (((size_t)b * NP_POLY + p) * NV + j) * 2;
    float sx = v[0], sy = v[1], ex = v[2], ey = v[3];
    float evx = ex - sx;
    float evy = ey - sy;
    float esq = fmaf(evx, evx, evy * evy);
    float rcp_esq = 1.0f / (esq + EPS);
    float slope = evy / (evx + EPS);
    float rcp_sl = 1.0f / (slope + EPS);
    g_seg4[idx] = make_float4(sx, sy, ex, ey);
    g_seg2[idx] = make_float2(rcp_esq, rcp_sl);
}

__global__ __launch_bounds__(THREADS)
void offroad_main_kernel(const float* __restrict__ points) {
    // block = ((b*NA + a) * NP_POLY + p)
    int bx = blockIdx.x;
    int p  = bx & (NP_POLY - 1);
    int ba = bx >> 4;                    // b*NA + a
    int b  = ba / NA;

    int wid = threadIdx.x >> 5;
    int ln  = threadIdx.x & 31;
    int t0  = wid * NPTS_WARP;

    float px[NPTS_WARP], py[NPTS_WARP], md[NPTS_WARP];
    int   ct[NPTS_WARP];

    const float2* pts2 = (const float2*)points;
#pragma unroll
    for (int k = 0; k < NPTS_WARP; k++) {
        int t = t0 + k;
        float2 pt = (t < NT) ? pts2[ba * NT + t] : make_float2(1e30f, 1e30f);
        px[k] = pt.x; py[k] = pt.y;
        md[k] = 3.4e38f;
        ct[k] = 0;
    }

    const float4* s4 = g_seg4 + (b * NSEG + p * SEG_PER_POLY);
    const float2* s2 = g_seg2 + (b * NSEG + p * SEG_PER_POLY);

    for (int s = ln; s < SEG_PER_POLY; s += 32) {
        float4 sg = __ldg(&s4[s]);
        float2 rr = __ldg(&s2[s]);
        float evx = sg.z - sg.x;
        float evy = sg.w - sg.y;
#pragma unroll
        for (int k = 0; k < NPTS_WARP; k++) {
            float v1x = px[k] - sg.x;
            float v1y = py[k] - sg.y;
            float dot = fmaf(v1x, evx, v1y * evy);
            float proj = __saturatef(dot * rr.x);
            float dx = fmaf(-evx, proj, v1x);       // px - (sx + evx*proj)
            float dy = fmaf(-evy, proj, v1y);
            float d2 = fmaf(dx, dx, dy * dy);
            md[k] = fminf(md[k], d2);
            // cond_y == (sy<=py) XOR (ey<=py)   (equivalent to reference form)
            bool c1 = (sg.y <= py[k]);
            bool c2 = (sg.w <= py[k]);
            float ix = fmaf(v1y, rr.y, sg.x);       // sx + (py-sy)/(slope+eps)
            ct[k] += ((c1 != c2) & (ix > px[k])) ? 1 : 0;
        }
    }

    // warp reduction
#pragma unroll
    for (int k = 0; k < NPTS_WARP; k++) {
#pragma unroll
        for (int o = 16; o > 0; o >>= 1) {
            md[k] = fminf(md[k], __shfl_xor_sync(0xffffffffu, md[k], o));
            ct[k] += __shfl_xor_sync(0xffffffffu, ct[k], o);
        }
    }

    if (ln == 0) {
#pragma unroll
        for (int k = 0; k < NPTS_WARP; k++) {
            int t = t0 + k;
            int idx = (ba * PTSLOTS + t) * NP_POLY + p;
            g_md[idx] = md[k];
            g_ct[idx] = ct[k];
        }
    }
}

__global__ __launch_bounds__(32)
void reduce_kernel(float* __restrict__ out) {
    int ba = blockIdx.x;   // 0..159
    int t  = threadIdx.x;  // 0..31
    float loss = 0.0f;
    if (t < NT) {
        float md = 3.4e38f;
        int ct = 0;
        const float* pm = g_md + (ba * PTSLOTS + t) * NP_POLY;
        const int*   pc = g_ct + (ba * PTSLOTS + t) * NP_POLY;
#pragma unroll
        for (int p = 0; p < NP_POLY; p++) {
            md = fminf(md, pm[p]);
            ct += pc[p];
        }
        float d = sqrtf(fmaxf(md, EPS));
        if (ct & 1) d = -d;
        loss = fmaxf(d + 0.5f, 0.0f);
    }
    // deterministic ordered-equivalent sum: warp shuffle tree (fixed order)
#pragma unroll
    for (int o = 16; o > 0; o >>= 1)
        loss += __shfl_xor_sync(0xffffffffu, loss, o);
    if (t == 0) out[ba] = loss;
}

extern "C" void kernel_launch(void* const* d_in, const int* in_sizes, int n_in,
                              void* d_out, int out_size) {
    const float* points = (const float*)d_in[0];  // (16,10,30,2)
    const float* polys  = (const float*)d_in[1];  // (16,16,200,2)
    float* out = (float*)d_out;                   // (16,10)

    int total = NB * NSEG;
    precompute_kernel<<<(total + 255) / 256, 256>>>(polys);
    offroad_main_kernel<<<NB * NA * NP_POLY, THREADS>>>(points);
    reduce_kernel<<<NB * NA, 32>>>(out);
}